// round 5
// baseline (speedup 1.0000x reference)
#include <cuda_runtime.h>
#include <math.h>

#define LIST_CAP    2048
#define W_CAP       (1 << 16)
#define BLOOM_WORDS 256            // 8192 bits
#define BLOOM_MASK  8191u
#define MAX_D       256
#define TSPLIT      4

__device__ float    g_W[W_CAP];      // recomputed every call (deterministic)
__device__ int4     g_list[LIST_CAP];// x=bq, y=t, z=dst
__device__ int      g_cnt;           // reset by fix
__device__ unsigned g_done;          // reset by fix

__device__ __forceinline__ float final_elem(float a1, float a2)
{
    float t1 = 1.0f / (1.0f + __expf(-a1));
    float t2 = 1.0f / (1.0f + __expf(-a2));
    float tp = t1 * t2;
    const float EPS = 1e-10f;
    return __logf((tp + EPS) / (1.0f - tp + EPS));
}

__global__ void k_all(const int* __restrict__ e_index,
                      const int* __restrict__ r_index,
                      const int* __restrict__ edge_index,
                      const int* __restrict__ edge_type,
                      const float* __restrict__ rel_emb,
                      const float* __restrict__ rel_proj,
                      const float* __restrict__ w_out,
                      float* __restrict__ out,
                      int E, int nBQ, int R, int D, int N, int outN,
                      int SB, int WB, int FB)
{
    int tid = threadIdx.x;
    int bid = blockIdx.x;

    __shared__ int      s_key[LIST_CAP];
    __shared__ float    s_wv[LIST_CAP];

    if (bid < SB) {
        // ---------- edge scan: append (bq, t, dst); no math ----------
        __shared__ int      s_e[64];
        __shared__ int      s_r_unused[1];
        __shared__ unsigned s_bloom[BLOOM_WORDS];
        (void)s_r_unused;
        for (int i = tid; i < BLOOM_WORDS; i += blockDim.x) s_bloom[i] = 0u;
        __syncthreads();
        if (tid < nBQ) {
            int ev = e_index[tid];
            s_e[tid] = ev;
            unsigned h = (unsigned)ev & BLOOM_MASK;
            atomicOr(&s_bloom[h >> 5], 1u << (h & 31u));
        }
        __syncthreads();

        int base = (bid * blockDim.x + tid) * 8;
        int srcs[8];
        if (base + 7 < E) {
            int4 a = *(const int4*)(edge_index + base);
            int4 b = *(const int4*)(edge_index + base + 4);
            srcs[0]=a.x; srcs[1]=a.y; srcs[2]=a.z; srcs[3]=a.w;
            srcs[4]=b.x; srcs[5]=b.y; srcs[6]=b.z; srcs[7]=b.w;
        } else {
            #pragma unroll
            for (int j = 0; j < 8; j++)
                srcs[j] = (base + j < E) ? edge_index[base + j] : -1;
        }

        #pragma unroll
        for (int j = 0; j < 8; j++) {
            int src = srcs[j];
            if (src < 0) continue;
            unsigned h = (unsigned)src & BLOOM_MASK;
            if (!((s_bloom[h >> 5] >> (h & 31u)) & 1u)) continue;
            // exact check (bloom false positives drop out here)
            unsigned long long mm = 0ull;
            for (int bq = 0; bq < nBQ; bq++)
                mm |= ((unsigned long long)(src == s_e[bq])) << bq;
            if (!mm) continue;
            int e   = base + j;
            int t   = edge_type[e];
            int dst = edge_index[E + e];
            while (mm) {
                int bq = __ffsll(mm) - 1;
                mm &= mm - 1;
                int idx = atomicAdd(&g_cnt, 1);
                if (idx < LIST_CAP) g_list[idx] = make_int4(bq, t, dst, 0);
            }
        }
    } else if (bid < SB + WB) {
        // ---------- W table: W[bq][t] = dot(rel_emb[r]*w_out, rel_proj[t]) ----------
        int widx  = bid - SB;
        int bq    = widx / TSPLIT;
        int chunk = widx - bq * TSPLIT;
        int tc    = (R + TSPLIT - 1) / TSPLIT;
        int tlo   = chunk * tc;
        int thi   = min(R, tlo + tc);

        __shared__ float v[MAX_D];
        int r = r_index[bq];
        for (int d = tid; d < D; d += blockDim.x)
            v[d] = rel_emb[(size_t)r * D + d] * w_out[d];
        __syncthreads();

        int warp = tid >> 5, lane = tid & 31, nw = blockDim.x >> 5;
        for (int t = tlo + warp; t < thi; t += nw) {
            const float* p = rel_proj + (size_t)t * D;
            float s = 0.0f;
            for (int d = lane; d < D; d += 32) s += v[d] * p[d];
            #pragma unroll
            for (int o = 16; o > 0; o >>= 1)
                s += __shfl_xor_sync(0xFFFFFFFFu, s, o);
            if (lane == 0) g_W[bq * R + t] = s;
        }
    } else {
        // ---------- const fill of out (grid-stride over fill blocks) ----------
        float cv = final_elem(0.0f, 0.0f);
        float4 cv4 = make_float4(cv, cv, cv, cv);
        int f  = bid - SB - WB;
        int n4 = outN >> 2;
        float4* out4 = (float4*)out;
        for (int k = f * blockDim.x + tid; k < n4; k += FB * blockDim.x)
            out4[k] = cv4;
        int tail = outN & 3;
        int i = f * blockDim.x + tid;
        if (i < tail) out[(n4 << 2) + i] = cv;
    }

    // ---------- last block: sparse fix-up ----------
    __threadfence();
    __shared__ bool isLast;
    if (tid == 0)
        isLast = (atomicAdd(&g_done, 1u) == (unsigned)gridDim.x - 1u);
    __syncthreads();
    if (!isLast) return;
    __threadfence();

    int cnt = *(volatile int*)&g_cnt;
    if (cnt > LIST_CAP) cnt = LIST_CAP;

    for (int i = tid; i < cnt; i += blockDim.x) {
        int4 en = g_list[i];
        s_key[i] = en.x * N + en.z;          // unique (bq, dst) key
        s_wv[i]  = g_W[en.x * R + en.y];
    }
    __syncthreads();

    for (int i = tid; i < cnt; i += blockDim.x) {
        int key = s_key[i];
        int bq  = key / N;
        int dst = key - bq * N;
        int b   = bq >> 1;
        int k1  = (2 * b) * N + dst;
        int k2  = k1 + N;
        float a1 = 0.0f, a2 = 0.0f;
        for (int jj = 0; jj < cnt; jj++) {
            int   kj = s_key[jj];
            float w  = s_wv[jj];
            if (kj == k1) a1 += w;
            if (kj == k2) a2 += w;
        }
        out[(size_t)b * N + dst] = final_elem(a1, a2);
    }
    __syncthreads();
    if (tid == 0) { g_cnt = 0; g_done = 0u; }
}

extern "C" void kernel_launch(void* const* d_in, const int* in_sizes, int n_in,
                              void* d_out, int out_size)
{
    // Input order: e_index, r_index, edge_index, edge_type, [num_nodes], rel_emb, rel_proj, w_out
    const int* e_index    = (const int*)d_in[0];
    const int* r_index    = (const int*)d_in[1];
    const int* edge_index = (const int*)d_in[2];
    const int* edge_type  = (const int*)d_in[3];
    int off = (n_in >= 8) ? 5 : 4;
    const float* rel_emb  = (const float*)d_in[off];
    const float* rel_proj = (const float*)d_in[off + 1];
    const float* w_out    = (const float*)d_in[off + 2];

    int nBQ = in_sizes[0];               // B*2
    int B   = nBQ / 2;
    int E   = in_sizes[3];               // edge_type is [E]
    int D   = in_sizes[off + 2];         // w_out is [D]
    int R   = in_sizes[off] / D;         // rel_emb is [R, D]
    int N   = out_size / B;              // output is [B, N]
    int outN = out_size;

    const int TPB = 256;
    int SB = (E + TPB * 8 - 1) / (TPB * 8);
    int WB = nBQ * TSPLIT;
    int n4 = outN >> 2;
    int FB = (n4 + TPB * 2 - 1) / (TPB * 2);   // ~2 float4 iterations per thread
    if (FB < 1) FB = 1;
    int grid = SB + WB + FB;

    k_all<<<grid, TPB>>>(e_index, r_index, edge_index, edge_type,
                         rel_emb, rel_proj, w_out, (float*)d_out,
                         E, nBQ, R, D, N, outN, SB, WB, FB);
}

// round 6
// speedup vs baseline: 1.4837x; 1.4837x over previous
#include <cuda_runtime.h>
#include <math.h>

#define ACC_CAP     (1 << 21)
#define LIST_CAP    4096
#define BLOOM_WORDS 256            // 8192 bits
#define BLOOM_MASK  8191u

__device__ float g_acc[ACC_CAP];   // zero-init; k_fix restores zeros each call
__device__ int2  g_list[LIST_CAP]; // (bq, dst)
__device__ int   g_cnt;            // reset by k_fix

__device__ __forceinline__ float final_elem(float a1, float a2)
{
    float t1 = 1.0f / (1.0f + __expf(-a1));
    float t2 = 1.0f / (1.0f + __expf(-a2));
    float tp = t1 * t2;
    const float EPS = 1e-10f;
    return __logf((tp + EPS) / (1.0f - tp + EPS));
}

// K1: blocks [0, SB): bloom-filtered edge scan, 8 edges/thread; on a match the
// warp cooperatively computes dot(rel_emb[r]*w_out, rel_proj[t]), accumulates
// into g_acc, and records (bq, dst).
// Blocks [SB, ...): const-fill out with final_elem(0,0).
__global__ void k_main(const int* __restrict__ e_index,
                       const int* __restrict__ r_index,
                       const int* __restrict__ edge_index,
                       const int* __restrict__ edge_type,
                       const float* __restrict__ rel_emb,
                       const float* __restrict__ rel_proj,
                       const float* __restrict__ w_out,
                       float* __restrict__ out,
                       int E, int nBQ, int D, int N, int outN, int SB, int FB)
{
    int tid = threadIdx.x;
    int bid = blockIdx.x;

    if (bid < SB) {
        __shared__ int      s_e[64];
        __shared__ int      s_r[64];
        __shared__ unsigned s_bloom[BLOOM_WORDS];
        for (int i = tid; i < BLOOM_WORDS; i += blockDim.x) s_bloom[i] = 0u;
        __syncthreads();
        if (tid < nBQ) {
            int ev = e_index[tid];
            s_e[tid] = ev;
            s_r[tid] = r_index[tid];
            unsigned h = (unsigned)ev & BLOOM_MASK;
            atomicOr(&s_bloom[h >> 5], 1u << (h & 31u));
        }
        __syncthreads();

        int base = (bid * blockDim.x + tid) * 8;
        int srcs[8];
        if (base + 7 < E) {
            int4 a = *(const int4*)(edge_index + base);
            int4 b = *(const int4*)(edge_index + base + 4);
            srcs[0]=a.x; srcs[1]=a.y; srcs[2]=a.z; srcs[3]=a.w;
            srcs[4]=b.x; srcs[5]=b.y; srcs[6]=b.z; srcs[7]=b.w;
        } else {
            #pragma unroll
            for (int j = 0; j < 8; j++)
                srcs[j] = (base + j < E) ? edge_index[base + j] : -1;
        }

        int lane = tid & 31;
        #pragma unroll
        for (int j = 0; j < 8; j++) {
            int src = srcs[j];
            bool maybe = false;
            if (src >= 0) {
                unsigned h = (unsigned)src & BLOOM_MASK;
                maybe = (s_bloom[h >> 5] >> (h & 31u)) & 1u;
            }
            if (!__ballot_sync(0xFFFFFFFFu, maybe)) continue;

            unsigned long long mm = 0ull;
            if (maybe) {
                for (int bq = 0; bq < nBQ; bq++)
                    mm |= ((unsigned long long)(src == s_e[bq])) << bq;
            }
            unsigned any = __ballot_sync(0xFFFFFFFFu, mm != 0ull);
            while (any) {
                int leader = __ffs(any) - 1;
                any &= any - 1;
                unsigned long long lm = __shfl_sync(0xFFFFFFFFu, mm, leader);
                int le  = __shfl_sync(0xFFFFFFFFu, base, leader) + j;
                int t   = edge_type[le];
                int dst = edge_index[E + le];
                const float* pt = rel_proj + (size_t)t * D;
                while (lm) {
                    int bq = __ffsll(lm) - 1;
                    lm &= lm - 1;
                    const float* pr = rel_emb + (size_t)s_r[bq] * D;
                    float s = 0.0f;
                    for (int d = lane; d < D; d += 32)
                        s += pr[d] * w_out[d] * pt[d];
                    #pragma unroll
                    for (int o = 16; o > 0; o >>= 1)
                        s += __shfl_xor_sync(0xFFFFFFFFu, s, o);
                    if (lane == 0) {
                        atomicAdd(&g_acc[(size_t)bq * N + dst], s);
                        int idx = atomicAdd(&g_cnt, 1);
                        if (idx < LIST_CAP) g_list[idx] = make_int2(bq, dst);
                    }
                }
            }
        }
    } else {
        // const fill: final_elem(0,0) = log(0.25/0.75), folded to a literal
        const float cv = -1.0986123f;
        float4 cv4 = make_float4(cv, cv, cv, cv);
        int f  = bid - SB;
        int n4 = outN >> 2;
        float4* out4 = (float4*)out;
        for (int k = f * blockDim.x + tid; k < n4; k += FB * blockDim.x)
            out4[k] = cv4;
        int tail = outN & 3;
        int i = f * blockDim.x + tid;
        if (i < tail) out[(n4 << 2) + i] = cv;
    }
}

// K2: single 1024-thread block; ~1 list entry per thread, so each phase is a
// single memory round-trip. Phase 1: recompute touched outputs (duplicate
// entries write identical values — benign). Phase 2: restore acc zeros, reset.
__global__ void k_fix(float* __restrict__ out, int N)
{
    int tid = threadIdx.x;
    int cnt = g_cnt;
    if (cnt > LIST_CAP) cnt = LIST_CAP;

    for (int i = tid; i < cnt; i += blockDim.x) {
        int2 en = g_list[i];
        int b = en.x >> 1, n = en.y;
        float a1 = g_acc[(size_t)(2 * b)     * N + n];
        float a2 = g_acc[(size_t)(2 * b + 1) * N + n];
        out[(size_t)b * N + n] = final_elem(a1, a2);
    }
    __syncthreads();
    for (int i = tid; i < cnt; i += blockDim.x) {
        int2 en = g_list[i];
        int b = en.x >> 1, n = en.y;
        g_acc[(size_t)(2 * b)     * N + n] = 0.0f;
        g_acc[(size_t)(2 * b + 1) * N + n] = 0.0f;
    }
    __syncthreads();
    if (tid == 0) g_cnt = 0;
}

extern "C" void kernel_launch(void* const* d_in, const int* in_sizes, int n_in,
                              void* d_out, int out_size)
{
    // Input order: e_index, r_index, edge_index, edge_type, [num_nodes], rel_emb, rel_proj, w_out
    const int* e_index    = (const int*)d_in[0];
    const int* r_index    = (const int*)d_in[1];
    const int* edge_index = (const int*)d_in[2];
    const int* edge_type  = (const int*)d_in[3];
    int off = (n_in >= 8) ? 5 : 4;
    const float* rel_emb  = (const float*)d_in[off];
    const float* rel_proj = (const float*)d_in[off + 1];
    const float* w_out    = (const float*)d_in[off + 2];

    int nBQ = in_sizes[0];               // B*2
    int B   = nBQ / 2;
    int E   = in_sizes[3];               // edge_type is [E]
    int D   = in_sizes[off + 2];         // w_out is [D]
    int N   = out_size / B;              // output is [B, N]
    int outN = out_size;

    const int TPB = 256;
    int SB = (E + TPB * 8 - 1) / (TPB * 8);
    int n4 = outN >> 2;
    int FB = (n4 + TPB * 2 - 1) / (TPB * 2);
    if (FB < 1) FB = 1;
    int grid = SB + FB;

    k_main<<<grid, TPB>>>(e_index, r_index, edge_index, edge_type,
                          rel_emb, rel_proj, w_out, (float*)d_out,
                          E, nBQ, D, N, outN, SB, FB);
    k_fix<<<1, 1024>>>((float*)d_out, N);
}